// round 13
// baseline (speedup 1.0000x reference)
#include <cuda_runtime.h>
#include <cstdint>

// ---------------------------------------------------------------------------
// GCNNet fused single-kernel implementation.
// An = D^-1/2 (A+I) D^-1/2, A = (mean_bands(graph) != 0). Dense pattern
// (measure-1 for Gaussian graph) => An = (1/30)*J (rank-1):
//   h1 = relu((1/30) colsum(real) @ W1 + b1)      (all rows identical)
//   h2 = relu(h1 @ W2 + b2)                       (An row-sums == 1)
//   x  = relu(h2 . Wlin + blin); out[c] = x * rowsum(Wconv[c]) + bconv[c]
// K processed in 4 chunks of 128, double-buffered colsums, depth-4 load ring.
// Graph-flag streaming is cut into 4 slices interleaved with the chunk loop
// (slices 0-2) and the layer-2 tail (slice 3), so every block issues DRAM
// traffic near-uniformly over its whole lifetime.
// ---------------------------------------------------------------------------

#define B_TOT   4096
#define BANDS   5
#define NN      30
#define IN_C    512
#define FF      128
#define CC      9
#define TB      8             // batches per block
#define SB      10            // padded batch stride (floats) in k-major smem

typedef unsigned long long u64t;

// ---- f32x2 helpers --------------------------------------------------------
__device__ __forceinline__ u64t pk2(float lo, float hi) {
    u64t r; asm("mov.b64 %0,{%1,%2};" : "=l"(r) : "f"(lo), "f"(hi)); return r;
}
__device__ __forceinline__ void upk2(float& lo, float& hi, u64t v) {
    asm("mov.b64 {%0,%1},%2;" : "=f"(lo), "=f"(hi) : "l"(v));
}
__device__ __forceinline__ void fma2(u64t& d, u64t a, u64t b) {
    asm("fma.rn.f32x2 %0,%1,%2,%0;" : "+l"(d) : "l"(a), "l"(b));
}

// ---------------------------------------------------------------------------
// one quarter-slice of the graph density flags: slice s covers group indices
// [450s, 450s+450) of the block's 1800 (= TB*225) float4 groups, i.e.
// batches 2s and 2s+1. Writes flagS[b]=0 on any zero off-diag mean.
// ---------------------------------------------------------------------------
__device__ __forceinline__ void flags_slice(
    int b0, int tid, int slice, const float* __restrict__ graph, int* flagS)
{
    for (int i = tid; i < 450; i += 256) {
        int gidx = slice * 450 + i;
        int b = gidx / 225, idx = gidx - b * 225;
        const float4* g4 = (const float4*)(graph + (size_t)(b0 + b) * (BANDS * NN * NN));
        float4 a0 = g4[idx];
        float4 a1 = g4[225 + idx];
        float4 a2 = g4[450 + idx];
        float4 a3 = g4[675 + idx];
        float4 a4 = g4[900 + idx];
        float s[4];
        s[0] = a0.x + a1.x + a2.x + a3.x + a4.x;
        s[1] = a0.y + a1.y + a2.y + a3.y + a4.y;
        s[2] = a0.z + a1.z + a2.z + a3.z + a4.z;
        s[3] = a0.w + a1.w + a2.w + a3.w + a4.w;
        bool bad = false;
        #pragma unroll
        for (int j = 0; j < 4; j++) {
            int p = idx * 4 + j;
            int n = p / NN, m = p - n * NN;
            if (n != m && s[j] * 0.2f == 0.0f) bad = true;
        }
        if (bad) flagS[b] = 0;
    }
}

// ---------------------------------------------------------------------------
// honest fallback for one non-dense batch; whole block (256 thr), smem 'buf'
// (>= 36728 bytes) is reused.
// ---------------------------------------------------------------------------
__device__ void fallback_batch(
    int b, char* buf, int tid,
    const float* __restrict__ real, const float* __restrict__ graph,
    const float* __restrict__ W1, const float* __restrict__ b1,
    const float* __restrict__ W2, const float* __restrict__ b2,
    const float* __restrict__ Wlin, const float* __restrict__ blin,
    const float* __restrict__ Wconv, const float* __restrict__ bconv,
    float* __restrict__ out)
{
    float* An   = (float*)buf;          // 900 (pad to 960 incl. dinv)
    float* dinv = An + 900;             // 30
    float* Ys   = An + 960;             // 3840
    float* Hs   = Ys + 3840;            // 3840
    float* rrow = Hs + 3840;            // 512
    float* xsb  = rrow + 512;           // 30     total 9182 floats = 36728 B

    const float* g = graph + (size_t)b * (BANDS * NN * NN);
    for (int p = tid; p < NN * NN; p += 256) {
        int n = p / NN, m = p - n * NN;
        float s5 = g[p] + g[900 + p] + g[1800 + p] + g[2700 + p] + g[3600 + p];
        float a = (s5 * 0.2f != 0.0f) ? 1.0f : 0.0f;
        if (n == m) a = 1.0f;
        An[p] = a;
    }
    __syncthreads();
    if (tid < NN) {
        float dg = 0.f;
        for (int m = 0; m < NN; m++) dg += An[tid * NN + m];
        dinv[tid] = (dg > 0.f) ? rsqrtf(dg) : 0.0f;
    }
    __syncthreads();
    for (int p = tid; p < NN * NN; p += 256) {
        int n = p / NN, m = p - n * NN;
        An[p] = dinv[n] * An[p] * dinv[m];
    }
    __syncthreads();

    const float* rb = real + (size_t)b * NN * IN_C;
    for (int n = 0; n < NN; n++) {
        for (int c = tid; c < IN_C; c += 256) rrow[c] = rb[n * IN_C + c];
        __syncthreads();
        if (tid < FF) {
            float accv = 0.f;
            for (int c = 0; c < IN_C; c++) accv += rrow[c] * W1[c * FF + tid];
            Ys[n * FF + tid] = accv;
        }
        __syncthreads();
    }
    if (tid < FF) {
        float bb = b1[tid];
        for (int n = 0; n < NN; n++) {
            float accv = 0.f;
            for (int m = 0; m < NN; m++) accv += An[n * NN + m] * Ys[m * FF + tid];
            Hs[n * FF + tid] = fmaxf(accv + bb, 0.0f);
        }
    }
    __syncthreads();
    if (tid < FF) {
        for (int n = 0; n < NN; n++) {
            float accv = 0.f;
            for (int c = 0; c < FF; c++) accv += Hs[n * FF + c] * W2[c * FF + tid];
            Ys[n * FF + tid] = accv;
        }
    }
    __syncthreads();
    if (tid < FF) {
        float bb = b2[tid];
        for (int n = 0; n < NN; n++) {
            float accv = 0.f;
            for (int m = 0; m < NN; m++) accv += An[n * NN + m] * Ys[m * FF + tid];
            Hs[n * FF + tid] = fmaxf(accv + bb, 0.0f);
        }
    }
    __syncthreads();
    if (tid < NN) {
        float accv = 0.f;
        for (int ff = 0; ff < FF; ff++) accv += Hs[tid * FF + ff] * Wlin[ff];
        xsb[tid] = fmaxf(accv + blin[0], 0.0f);
    }
    __syncthreads();
    if (tid < CC) {
        float accv = bconv[tid];
        for (int n = 0; n < NN; n++) accv += xsb[n] * Wconv[tid * NN + n];
        out[(size_t)b * CC + tid] = accv;
    }
    __syncthreads();
}

// ---------------------------------------------------------------------------
// fused kernel: grid 512, block 256, TB=8 batches/block, 4 blocks/SM.
// Warp w: kh = w>>1 (K quarter within chunk), bh = w&1 (batch half).
// For colsum streaming, warp w owns batch w. Lane: f = 4*lane.
// ---------------------------------------------------------------------------
__global__ void __launch_bounds__(256, 4) fused_gcn(
    const float* __restrict__ real, const float* __restrict__ graph,
    const float* __restrict__ W1, const float* __restrict__ b1,
    const float* __restrict__ W2, const float* __restrict__ b2,
    const float* __restrict__ Wlin, const float* __restrict__ blin,
    const float* __restrict__ Wconv, const float* __restrict__ bconv,
    float* __restrict__ out)
{
    // buf layout (time-multiplexed):
    //   layer-1 pipeline: ubuf0 [128][SB] @ 0 (5120 B), ubuf1 @ 5120 (5120 B)
    //   reductions: red64 [4 kh][4 g][128 f] u64 @ 0    (16384 B)
    //   h1T [128][SB] floats @ 32768                    ( 5120 B)
    //   fallback: 36728 B from 0
    __shared__ __align__(16) char buf[38400];
    __shared__ float xp[8][4];
    __shared__ float xs[TB];
    __shared__ float wsum[CC];
    __shared__ int   flagS[TB];

    float* ub0   = (float*)buf;
    float* ub1   = (float*)(buf + 5120);
    u64t*  red64 = (u64t*)buf;
    float* h1T   = (float*)(buf + 32768);

    const int tid  = threadIdx.x;
    const int b0   = blockIdx.x * TB;
    const int w    = tid >> 5;          // warp 0..7
    const int lane = tid & 31;
    const int f4   = lane * 4;
    const int kh   = w >> 1;            // 0..3
    const int bh   = w & 1;             // 0..1

    if (tid < TB) flagS[tid] = 1;
    if (tid < CC) {
        float a = 0.f;
        #pragma unroll
        for (int n = 0; n < NN; n++) a += Wconv[tid * NN + n];
        wsum[tid] = a;
    }
    __syncthreads();

    // ---- layer-1 pipeline over 4 K-chunks of 128.
    // Warp w streams colsums of batch w; FMA role: (kh, bh).
    const float4* rb4 = (const float4*)(real + (size_t)(b0 + w) * NN * IN_C);

    // prologue: colsum of chunk 0 -> ub0
    {
        float4 a = make_float4(0.f, 0.f, 0.f, 0.f);
        #pragma unroll 6
        for (int n = 0; n < NN; n++) {
            float4 v = rb4[n * (IN_C / 4) + lane];
            a.x += v.x; a.y += v.y; a.z += v.z; a.w += v.w;
        }
        int kb = lane * 4;
        ub0[(kb + 0) * SB + w] = a.x;
        ub0[(kb + 1) * SB + w] = a.y;
        ub0[(kb + 2) * SB + w] = a.z;
        ub0[(kb + 3) * SB + w] = a.w;
    }
    __syncthreads();

    u64t acc[2][4];
    #pragma unroll
    for (int p = 0; p < 2; p++)
        #pragma unroll
        for (int j = 0; j < 4; j++) acc[p][j] = 0ull;

    for (int c = 0; c < 4; c++) {
        float* ub = (c & 1) ? ub1 : ub0;
        float* un = (c & 1) ? ub0 : ub1;
        const bool more = (c < 3);
        const float4* nxt = rb4 + (c + 1) * 32 + lane;    // rows of next chunk
        float4 a = make_float4(0.f, 0.f, 0.f, 0.f);
        const int kbeg = kh * 32;                         // within chunk
        const float4* Wp = (const float4*)(W1 + (size_t)(c * 128 + kbeg) * FF) + lane;
        float4 wpf[2];
        wpf[0] = Wp[0];
        wpf[1] = Wp[FF / 4];

        // depth-4 ring on streamed loads: slot ki&3 holds row ki.
        float4 vr[4];
        if (more) {
            #pragma unroll
            for (int s = 0; s < 4; s++) vr[s] = nxt[s * (IN_C / 4)];
        }
        #pragma unroll
        for (int ki = 0; ki < 32; ki++) {
            float4 v;
            bool cons = more && (ki < NN);
            if (cons) v = vr[ki & 3];                     // row ki (loaded ki-4)
            if (more && (ki + 4 < NN))
                vr[ki & 3] = nxt[(ki + 4) * (IN_C / 4)];  // refill slot: row ki+4
            float4 wv = wpf[ki & 1];
            if (ki + 2 < 32) wpf[ki & 1] = Wp[(ki + 2) * (FF / 4)];
            const float* up = &ub[(kbeg + ki) * SB + bh * 4];
            u64t u0 = *(const u64t*)(up + 0);
            u64t u1 = *(const u64t*)(up + 2);
            u64t w0 = pk2(wv.x, wv.x), w1 = pk2(wv.y, wv.y);
            u64t w2 = pk2(wv.z, wv.z), w3 = pk2(wv.w, wv.w);
            fma2(acc[0][0], u0, w0); fma2(acc[1][0], u1, w0);
            fma2(acc[0][1], u0, w1); fma2(acc[1][1], u1, w1);
            fma2(acc[0][2], u0, w2); fma2(acc[1][2], u1, w2);
            fma2(acc[0][3], u0, w3); fma2(acc[1][3], u1, w3);
            if (cons) { a.x += v.x; a.y += v.y; a.z += v.z; a.w += v.w; }
        }
        __syncthreads();          // ub reads done; un's previous readers done
        if (more) {
            int kb = lane * 4;
            un[(kb + 0) * SB + w] = a.x;
            un[(kb + 1) * SB + w] = a.y;
            un[(kb + 2) * SB + w] = a.z;
            un[(kb + 3) * SB + w] = a.w;
        }
        __syncthreads();          // un visible for next iteration

        // ---- flags slice c (chunks 0-2): keeps DRAM fed during the loop
        // phase; slice 3 runs in the layer-2 tail below.
        if (c < 3)
            flags_slice(b0, tid, c, graph, flagS);
    }

    // ---- stash layer-1 partials (red64 aliases the dead ubuf region)
    #pragma unroll
    for (int p = 0; p < 2; p++)
        #pragma unroll
        for (int j = 0; j < 4; j++)
            red64[kh * 512 + (bh * 2 + p) * 128 + f4 + j] = acc[p][j];
    __syncthreads();

    // ---- reduce kh -> h1T. Thread t: f = t&127, gg = t>>7; g = gg, gg+2.
    {
        const float s1 = 1.0f / 30.0f;
        int fr = tid & 127, gg = tid >> 7;
        float bb = b1[fr];
        #pragma unroll
        for (int pi = 0; pi < 2; pi++) {
            int g = gg + 2 * pi;
            float lo = 0.f, hi = 0.f;
            #pragma unroll
            for (int q = 0; q < 4; q++) {
                float av, bv; upk2(av, bv, red64[q * 512 + g * 128 + fr]);
                lo += av; hi += bv;
            }
            h1T[fr * SB + 2 * g]     = fmaxf(fmaf(s1, lo, bb), 0.0f);
            h1T[fr * SB + 2 * g + 1] = fmaxf(fmaf(s1, hi, bb), 0.0f);
        }
    }
    __syncthreads();

    // ---- layer-2 partials. Warp: k in [kh*32, kh*32+32).
    #pragma unroll
    for (int p = 0; p < 2; p++)
        #pragma unroll
        for (int j = 0; j < 4; j++) acc[p][j] = 0ull;
    {
        const int kbeg = kh * 32;
        const float4* Wp = (const float4*)(W2 + (size_t)kbeg * FF) + lane;
        float4 wpf[2];
        wpf[0] = Wp[0];
        wpf[1] = Wp[FF / 4];
        #pragma unroll 4
        for (int ki = 0; ki < 32; ki++) {
            float4 wv = wpf[ki & 1];
            int kn = (ki + 2 < 32) ? (ki + 2) : ki;
            wpf[ki & 1] = Wp[kn * (FF / 4)];
            const float* up = &h1T[(kbeg + ki) * SB + bh * 4];
            u64t u0 = *(const u64t*)(up + 0);
            u64t u1 = *(const u64t*)(up + 2);
            u64t w0 = pk2(wv.x, wv.x), w1 = pk2(wv.y, wv.y);
            u64t w2 = pk2(wv.z, wv.z), w3 = pk2(wv.w, wv.w);
            fma2(acc[0][0], u0, w0); fma2(acc[1][0], u1, w0);
            fma2(acc[0][1], u0, w1); fma2(acc[1][1], u1, w1);
            fma2(acc[0][2], u0, w2); fma2(acc[1][2], u1, w2);
            fma2(acc[0][3], u0, w3); fma2(acc[1][3], u1, w3);
        }
    }
    __syncthreads();   // h1T reads done (red64 write below doesn't touch h1T)
    #pragma unroll
    for (int p = 0; p < 2; p++)
        #pragma unroll
        for (int j = 0; j < 4; j++)
            red64[kh * 512 + (bh * 2 + p) * 128 + f4 + j] = acc[p][j];

    // ---- flags slice 3: streams DRAM during the compute tail.
    flags_slice(b0, tid, 3, graph, flagS);
    __syncthreads();

    // ---- final reduce + epilogue. Thread t: f = t&127, gg = t>>7.
    {
        int fr = tid & 127, gg = tid >> 7;
        float bb = b2[fr];
        float wl = Wlin[fr];
        float part[4];                     // {g=gg: lo,hi ; g=gg+2: lo,hi}
        #pragma unroll
        for (int pi = 0; pi < 2; pi++) {
            int g = gg + 2 * pi;
            float lo = 0.f, hi = 0.f;
            #pragma unroll
            for (int q = 0; q < 4; q++) {
                float av, bv; upk2(av, bv, red64[q * 512 + g * 128 + fr]);
                lo += av; hi += bv;
            }
            part[2 * pi]     = fmaxf(lo + bb, 0.0f) * wl;
            part[2 * pi + 1] = fmaxf(hi + bb, 0.0f) * wl;
        }
        #pragma unroll
        for (int off = 16; off > 0; off >>= 1)
            #pragma unroll
            for (int cc = 0; cc < 4; cc++)
                part[cc] += __shfl_xor_sync(0xffffffffu, part[cc], off);
        if (lane == 0) {
            xp[w][0] = part[0]; xp[w][1] = part[1];
            xp[w][2] = part[2]; xp[w][3] = part[3];
        }
    }
    __syncthreads();
    if (tid < TB) {
        int b = tid;
        int g  = b >> 1;
        int gg = g & 1;                    // warps gg*4..gg*4+3 hold this g
        int slot = (g >> 1) * 2 + (b & 1);
        float s = xp[gg * 4 + 0][slot] + xp[gg * 4 + 1][slot]
                + xp[gg * 4 + 2][slot] + xp[gg * 4 + 3][slot];
        xs[b] = fmaxf(s + blin[0], 0.0f);
    }
    __syncthreads();

    if (tid < TB * CC) {
        int b = tid / CC, c = tid - b * CC;
        if (flagS[b])
            out[(size_t)(b0 + b) * CC + c] = xs[b] * wsum[c] + bconv[c];
    }
    __syncthreads();

    // ---- honest fallback for any non-dense batch (uniform branch)
    for (int fb = 0; fb < TB; fb++) {
        if (!flagS[fb]) {
            fallback_batch(b0 + fb, buf, tid, real, graph, W1, b1, W2, b2,
                           Wlin, blin, Wconv, bconv, out);
        }
    }
}

// ---------------------------------------------------------------------------
extern "C" void kernel_launch(void* const* d_in, const int* in_sizes, int n_in,
                              void* d_out, int out_size)
{
    const float* real  = (const float*)d_in[0];
    const float* graph = (const float*)d_in[2];
    const float* W1    = (const float*)d_in[3];
    const float* b1    = (const float*)d_in[4];
    const float* W2    = (const float*)d_in[5];
    const float* b2    = (const float*)d_in[6];
    const float* Wlin  = (const float*)d_in[7];
    const float* blin  = (const float*)d_in[8];
    const float* Wconv = (const float*)d_in[9];
    const float* bconv = (const float*)d_in[10];
    float* out = (float*)d_out;

    fused_gcn<<<B_TOT / TB, 256>>>(real, graph, W1, b1, W2, b2, Wlin, blin,
                                   Wconv, bconv, out);
}

// round 15
// speedup vs baseline: 1.0851x; 1.0851x over previous
#include <cuda_runtime.h>
#include <cstdint>

// ---------------------------------------------------------------------------
// GCNNet fused single-kernel implementation.
// An = D^-1/2 (A+I) D^-1/2, A = (mean_bands(graph) != 0). Dense pattern
// (measure-1 for Gaussian graph) => An = (1/30)*J (rank-1):
//   h1 = relu((1/30) colsum(real) @ W1 + b1)      (all rows identical)
//   h2 = relu(h1 @ W2 + b2)                       (An row-sums == 1)
//   x  = relu(h2 . Wlin + blin); out[c] = x * rowsum(Wconv[c]) + bconv[c]
// K processed in 4 chunks of 128, double-buffered colsums, depth-4 load ring.
// Tail warp-split: after layer-1 partials are stashed, warps 0-3 run the
// whole compute tail (h1-reduce, layer-2, epilogue; named barrier 1) while
// warps 4-7 stream the graph density flags (pure DRAM) — so the compute
// tail hides under the flags stream instead of idling the chip's DRAM.
// ---------------------------------------------------------------------------

#define B_TOT   4096
#define BANDS   5
#define NN      30
#define IN_C    512
#define FF      128
#define CC      9
#define TB      8             // batches per block
#define SB      10            // padded batch stride (floats) in k-major smem

typedef unsigned long long u64t;

// ---- f32x2 helpers --------------------------------------------------------
__device__ __forceinline__ u64t pk2(float lo, float hi) {
    u64t r; asm("mov.b64 %0,{%1,%2};" : "=l"(r) : "f"(lo), "f"(hi)); return r;
}
__device__ __forceinline__ void upk2(float& lo, float& hi, u64t v) {
    asm("mov.b64 {%0,%1},%2;" : "=f"(lo), "=f"(hi) : "l"(v));
}
__device__ __forceinline__ void fma2(u64t& d, u64t a, u64t b) {
    asm("fma.rn.f32x2 %0,%1,%2,%0;" : "+l"(d) : "l"(a), "l"(b));
}

// ---------------------------------------------------------------------------
// honest fallback for one non-dense batch; whole block (256 thr), smem 'buf'
// (>= 36728 bytes) is reused.
// ---------------------------------------------------------------------------
__device__ void fallback_batch(
    int b, char* buf, int tid,
    const float* __restrict__ real, const float* __restrict__ graph,
    const float* __restrict__ W1, const float* __restrict__ b1,
    const float* __restrict__ W2, const float* __restrict__ b2,
    const float* __restrict__ Wlin, const float* __restrict__ blin,
    const float* __restrict__ Wconv, const float* __restrict__ bconv,
    float* __restrict__ out)
{
    float* An   = (float*)buf;          // 900 (pad to 960 incl. dinv)
    float* dinv = An + 900;             // 30
    float* Ys   = An + 960;             // 3840
    float* Hs   = Ys + 3840;            // 3840
    float* rrow = Hs + 3840;            // 512
    float* xsb  = rrow + 512;           // 30     total 9182 floats = 36728 B

    const float* g = graph + (size_t)b * (BANDS * NN * NN);
    for (int p = tid; p < NN * NN; p += 256) {
        int n = p / NN, m = p - n * NN;
        float s5 = g[p] + g[900 + p] + g[1800 + p] + g[2700 + p] + g[3600 + p];
        float a = (s5 * 0.2f != 0.0f) ? 1.0f : 0.0f;
        if (n == m) a = 1.0f;
        An[p] = a;
    }
    __syncthreads();
    if (tid < NN) {
        float dg = 0.f;
        for (int m = 0; m < NN; m++) dg += An[tid * NN + m];
        dinv[tid] = (dg > 0.f) ? rsqrtf(dg) : 0.0f;
    }
    __syncthreads();
    for (int p = tid; p < NN * NN; p += 256) {
        int n = p / NN, m = p - n * NN;
        An[p] = dinv[n] * An[p] * dinv[m];
    }
    __syncthreads();

    const float* rb = real + (size_t)b * NN * IN_C;
    for (int n = 0; n < NN; n++) {
        for (int c = tid; c < IN_C; c += 256) rrow[c] = rb[n * IN_C + c];
        __syncthreads();
        if (tid < FF) {
            float accv = 0.f;
            for (int c = 0; c < IN_C; c++) accv += rrow[c] * W1[c * FF + tid];
            Ys[n * FF + tid] = accv;
        }
        __syncthreads();
    }
    if (tid < FF) {
        float bb = b1[tid];
        for (int n = 0; n < NN; n++) {
            float accv = 0.f;
            for (int m = 0; m < NN; m++) accv += An[n * NN + m] * Ys[m * FF + tid];
            Hs[n * FF + tid] = fmaxf(accv + bb, 0.0f);
        }
    }
    __syncthreads();
    if (tid < FF) {
        for (int n = 0; n < NN; n++) {
            float accv = 0.f;
            for (int c = 0; c < FF; c++) accv += Hs[n * FF + c] * W2[c * FF + tid];
            Ys[n * FF + tid] = accv;
        }
    }
    __syncthreads();
    if (tid < FF) {
        float bb = b2[tid];
        for (int n = 0; n < NN; n++) {
            float accv = 0.f;
            for (int m = 0; m < NN; m++) accv += An[n * NN + m] * Ys[m * FF + tid];
            Hs[n * FF + tid] = fmaxf(accv + bb, 0.0f);
        }
    }
    __syncthreads();
    if (tid < NN) {
        float accv = 0.f;
        for (int ff = 0; ff < FF; ff++) accv += Hs[tid * FF + ff] * Wlin[ff];
        xsb[tid] = fmaxf(accv + blin[0], 0.0f);
    }
    __syncthreads();
    if (tid < CC) {
        float accv = bconv[tid];
        for (int n = 0; n < NN; n++) accv += xsb[n] * Wconv[tid * NN + n];
        out[(size_t)b * CC + tid] = accv;
    }
    __syncthreads();
}

// ---------------------------------------------------------------------------
// fused kernel: grid 512, block 256, TB=8 batches/block, 4 blocks/SM.
// Layer-1: warp w: kh = w>>1 (K quarter in chunk), bh = w&1 (batch half).
// For colsum streaming, warp w owns batch w. Lane: f = 4*lane.
// Tail: warps 0-3 compute (layer-2 etc., bar.sync 1), warps 4-7 flags.
// ---------------------------------------------------------------------------
__global__ void __launch_bounds__(256, 4) fused_gcn(
    const float* __restrict__ real, const float* __restrict__ graph,
    const float* __restrict__ W1, const float* __restrict__ b1,
    const float* __restrict__ W2, const float* __restrict__ b2,
    const float* __restrict__ Wlin, const float* __restrict__ blin,
    const float* __restrict__ Wconv, const float* __restrict__ bconv,
    float* __restrict__ out)
{
    // buf layout (time-multiplexed):
    //   layer-1 pipeline: ubuf0 [128][SB] @ 0 (5120 B), ubuf1 @ 5120 (5120 B)
    //   reductions: red64 [q][4 g][128 f] u64 @ 0 (16384 B; layer1 q=4, layer2 q=2)
    //   h1T [128][SB] floats @ 32768                    ( 5120 B)
    //   fallback: 36728 B from 0
    __shared__ __align__(16) char buf[38400];
    __shared__ float xp[4][8];
    __shared__ float xs[TB];
    __shared__ float wsum[CC];
    __shared__ int   flagS[TB];

    float* ub0   = (float*)buf;
    float* ub1   = (float*)(buf + 5120);
    u64t*  red64 = (u64t*)buf;
    float* h1T   = (float*)(buf + 32768);

    const int tid  = threadIdx.x;
    const int b0   = blockIdx.x * TB;
    const int w    = tid >> 5;          // warp 0..7
    const int lane = tid & 31;
    const int f4   = lane * 4;
    const int kh   = w >> 1;            // 0..3 (layer-1)
    const int bh   = w & 1;             // 0..1 (layer-1)

    if (tid < TB) flagS[tid] = 1;
    if (tid < CC) {
        float a = 0.f;
        #pragma unroll
        for (int n = 0; n < NN; n++) a += Wconv[tid * NN + n];
        wsum[tid] = a;
    }
    __syncthreads();

    // ---- layer-1 pipeline over 4 K-chunks of 128.
    // Warp w streams colsums of batch w; FMA role: (kh, bh).
    const float4* rb4 = (const float4*)(real + (size_t)(b0 + w) * NN * IN_C);

    // prologue: colsum of chunk 0 -> ub0
    {
        float4 a = make_float4(0.f, 0.f, 0.f, 0.f);
        #pragma unroll 6
        for (int n = 0; n < NN; n++) {
            float4 v = rb4[n * (IN_C / 4) + lane];
            a.x += v.x; a.y += v.y; a.z += v.z; a.w += v.w;
        }
        int kb = lane * 4;
        ub0[(kb + 0) * SB + w] = a.x;
        ub0[(kb + 1) * SB + w] = a.y;
        ub0[(kb + 2) * SB + w] = a.z;
        ub0[(kb + 3) * SB + w] = a.w;
    }
    __syncthreads();

    u64t acc[2][4];
    #pragma unroll
    for (int p = 0; p < 2; p++)
        #pragma unroll
        for (int j = 0; j < 4; j++) acc[p][j] = 0ull;

    for (int c = 0; c < 4; c++) {
        float* ub = (c & 1) ? ub1 : ub0;
        float* un = (c & 1) ? ub0 : ub1;
        const bool more = (c < 3);
        const float4* nxt = rb4 + (c + 1) * 32 + lane;    // rows of next chunk
        float4 a = make_float4(0.f, 0.f, 0.f, 0.f);
        const int kbeg = kh * 32;                         // within chunk
        const float4* Wp = (const float4*)(W1 + (size_t)(c * 128 + kbeg) * FF) + lane;
        float4 wpf[2];
        wpf[0] = Wp[0];
        wpf[1] = Wp[FF / 4];

        // depth-4 ring on streamed loads: slot ki&3 holds row ki.
        float4 vr[4];
        if (more) {
            #pragma unroll
            for (int s = 0; s < 4; s++) vr[s] = nxt[s * (IN_C / 4)];
        }
        #pragma unroll
        for (int ki = 0; ki < 32; ki++) {
            float4 v;
            bool cons = more && (ki < NN);
            if (cons) v = vr[ki & 3];                     // row ki (loaded ki-4)
            if (more && (ki + 4 < NN))
                vr[ki & 3] = nxt[(ki + 4) * (IN_C / 4)];  // refill slot: row ki+4
            float4 wv = wpf[ki & 1];
            if (ki + 2 < 32) wpf[ki & 1] = Wp[(ki + 2) * (FF / 4)];
            const float* up = &ub[(kbeg + ki) * SB + bh * 4];
            u64t u0 = *(const u64t*)(up + 0);
            u64t u1 = *(const u64t*)(up + 2);
            u64t w0 = pk2(wv.x, wv.x), w1 = pk2(wv.y, wv.y);
            u64t w2 = pk2(wv.z, wv.z), w3 = pk2(wv.w, wv.w);
            fma2(acc[0][0], u0, w0); fma2(acc[1][0], u1, w0);
            fma2(acc[0][1], u0, w1); fma2(acc[1][1], u1, w1);
            fma2(acc[0][2], u0, w2); fma2(acc[1][2], u1, w2);
            fma2(acc[0][3], u0, w3); fma2(acc[1][3], u1, w3);
            if (cons) { a.x += v.x; a.y += v.y; a.z += v.z; a.w += v.w; }
        }
        __syncthreads();          // ub reads done; un's previous readers done
        if (more) {
            int kb = lane * 4;
            un[(kb + 0) * SB + w] = a.x;
            un[(kb + 1) * SB + w] = a.y;
            un[(kb + 2) * SB + w] = a.z;
            un[(kb + 3) * SB + w] = a.w;
        }
        __syncthreads();          // un visible for next iteration
    }

    // ---- stash layer-1 partials (red64 aliases the dead ubuf region)
    #pragma unroll
    for (int p = 0; p < 2; p++)
        #pragma unroll
        for (int j = 0; j < 4; j++)
            red64[kh * 512 + (bh * 2 + p) * 128 + f4 + j] = acc[p][j];
    __syncthreads();

    // ========================== TAIL WARP-SPLIT ============================
    if (w < 4) {
        // ---- compute tail on warps 0-3 (128 threads, barrier id 1) ----
        // h1-reduce: thread fr = tid (0..127) handles all 4 batch-pairs.
        {
            const float s1 = 1.0f / 30.0f;
            float bb = b1[tid];
            #pragma unroll
            for (int g = 0; g < 4; g++) {
                float lo = 0.f, hi = 0.f;
                #pragma unroll
                for (int q = 0; q < 4; q++) {
                    float av, bv; upk2(av, bv, red64[q * 512 + g * 128 + tid]);
                    lo += av; hi += bv;
                }
                h1T[tid * SB + 2 * g]     = fmaxf(fmaf(s1, lo, bb), 0.0f);
                h1T[tid * SB + 2 * g + 1] = fmaxf(fmaf(s1, hi, bb), 0.0f);
            }
        }
        asm volatile("bar.sync 1, 128;" ::: "memory");

        // layer-2 partials: warp w: kh2 = w>>1 (k in [64*kh2, +64)), bh2 = w&1.
        u64t a2[2][4];
        #pragma unroll
        for (int p = 0; p < 2; p++)
            #pragma unroll
            for (int j = 0; j < 4; j++) a2[p][j] = 0ull;
        {
            const int kh2 = w >> 1, bh2 = w & 1;
            const int kbeg = kh2 * 64;
            const float4* Wp = (const float4*)(W2 + (size_t)kbeg * FF) + lane;
            float4 wpf[2];
            wpf[0] = Wp[0];
            wpf[1] = Wp[FF / 4];
            #pragma unroll 4
            for (int ki = 0; ki < 64; ki++) {
                float4 wv = wpf[ki & 1];
                int kn = (ki + 2 < 64) ? (ki + 2) : ki;
                wpf[ki & 1] = Wp[kn * (FF / 4)];
                const float* up = &h1T[(kbeg + ki) * SB + bh2 * 4];
                u64t u0 = *(const u64t*)(up + 0);
                u64t u1 = *(const u64t*)(up + 2);
                u64t w0 = pk2(wv.x, wv.x), w1 = pk2(wv.y, wv.y);
                u64t w2 = pk2(wv.z, wv.z), w3 = pk2(wv.w, wv.w);
                fma2(a2[0][0], u0, w0); fma2(a2[1][0], u1, w0);
                fma2(a2[0][1], u0, w1); fma2(a2[1][1], u1, w1);
                fma2(a2[0][2], u0, w2); fma2(a2[1][2], u1, w2);
                fma2(a2[0][3], u0, w3); fma2(a2[1][3], u1, w3);
            }
            asm volatile("bar.sync 1, 128;" ::: "memory"); // h1T reads done
            #pragma unroll
            for (int p = 0; p < 2; p++)
                #pragma unroll
                for (int j = 0; j < 4; j++)
                    red64[kh2 * 512 + (bh2 * 2 + p) * 128 + f4 + j] = a2[p][j];
        }
        asm volatile("bar.sync 1, 128;" ::: "memory");

        // final reduce + epilogue: thread fr = tid, all 8 (g,lo/hi) slots.
        {
            float bb = b2[tid];
            float wl = Wlin[tid];
            float part[8];
            #pragma unroll
            for (int g = 0; g < 4; g++) {
                float lo = 0.f, hi = 0.f;
                #pragma unroll
                for (int q = 0; q < 2; q++) {
                    float av, bv; upk2(av, bv, red64[q * 512 + g * 128 + tid]);
                    lo += av; hi += bv;
                }
                part[2 * g]     = fmaxf(lo + bb, 0.0f) * wl;
                part[2 * g + 1] = fmaxf(hi + bb, 0.0f) * wl;
            }
            #pragma unroll
            for (int off = 16; off > 0; off >>= 1)
                #pragma unroll
                for (int s = 0; s < 8; s++)
                    part[s] += __shfl_xor_sync(0xffffffffu, part[s], off);
            if (lane == 0) {
                #pragma unroll
                for (int s = 0; s < 8; s++) xp[w][s] = part[s];
            }
        }
        asm volatile("bar.sync 1, 128;" ::: "memory");
        // slot s corresponds directly to batch s (pair g={s>>1}, lo/hi={s&1})
        if (tid < TB) {
            float s = xp[0][tid] + xp[1][tid] + xp[2][tid] + xp[3][tid];
            xs[tid] = fmaxf(s + blin[0], 0.0f);
        }
    } else {
        // ---- flags streaming on warps 4-7 (128 threads): full graph check.
        for (int i = tid - 128; i < TB * 225; i += 128) {
            int b = i / 225, idx = i - b * 225;
            const float4* g4 = (const float4*)(graph + (size_t)(b0 + b) * (BANDS * NN * NN));
            float4 a0 = g4[idx];
            float4 a1 = g4[225 + idx];
            float4 a2v = g4[450 + idx];
            float4 a3 = g4[675 + idx];
            float4 a4 = g4[900 + idx];
            float s[4];
            s[0] = a0.x + a1.x + a2v.x + a3.x + a4.x;
            s[1] = a0.y + a1.y + a2v.y + a3.y + a4.y;
            s[2] = a0.z + a1.z + a2v.z + a3.z + a4.z;
            s[3] = a0.w + a1.w + a2v.w + a3.w + a4.w;
            bool bad = false;
            #pragma unroll
            for (int j = 0; j < 4; j++) {
                int p = idx * 4 + j;
                int n = p / NN, m = p - n * NN;
                if (n != m && s[j] * 0.2f == 0.0f) bad = true;
            }
            if (bad) flagS[b] = 0;
        }
    }
    __syncthreads();   // join compute warps and flags warps

    if (tid < TB * CC) {
        int b = tid / CC, c = tid - b * CC;
        if (flagS[b])
            out[(size_t)(b0 + b) * CC + c] = xs[b] * wsum[c] + bconv[c];
    }
    __syncthreads();

    // ---- honest fallback for any non-dense batch (uniform branch)
    for (int fb = 0; fb < TB; fb++) {
        if (!flagS[fb]) {
            fallback_batch(b0 + fb, buf, tid, real, graph, W1, b1, W2, b2,
                           Wlin, blin, Wconv, bconv, out);
        }
    }
}

// ---------------------------------------------------------------------------
extern "C" void kernel_launch(void* const* d_in, const int* in_sizes, int n_in,
                              void* d_out, int out_size)
{
    const float* real  = (const float*)d_in[0];
    const float* graph = (const float*)d_in[2];
    const float* W1    = (const float*)d_in[3];
    const float* b1    = (const float*)d_in[4];
    const float* W2    = (const float*)d_in[5];
    const float* b2    = (const float*)d_in[6];
    const float* Wlin  = (const float*)d_in[7];
    const float* blin  = (const float*)d_in[8];
    const float* Wconv = (const float*)d_in[9];
    const float* bconv = (const float*)d_in[10];
    float* out = (float*)d_out;

    fused_gcn<<<B_TOT / TB, 256>>>(real, graph, W1, b1, W2, b2, Wlin, blin,
                                   Wconv, bconv, out);
}

// round 16
// speedup vs baseline: 1.1435x; 1.0538x over previous
#include <cuda_runtime.h>
#include <cstdint>

// ---------------------------------------------------------------------------
// GCNNet fused single-kernel implementation.
// An = D^-1/2 (A+I) D^-1/2, A = (mean_bands(graph) != 0). Dense pattern
// (measure-1 for Gaussian graph) => An = (1/30)*J (rank-1):
//   h1 = relu((1/30) colsum(real) @ W1 + b1)      (all rows identical)
//   h2 = relu(h1 @ W2 + b2)                       (An row-sums == 1)
//   x  = relu(h2 . Wlin + blin); out[c] = x * rowsum(Wconv[c]) + bconv[c]
// Shape: 128-thread blocks, TB=4 batches, grid 1024, 8 blocks/SM. Many small
// independent blocks desynchronize naturally, so DRAM stays fed while other
// blocks compute (vs 4 big barrier-locked blocks). K in 4 chunks of 128 with
// double-buffered colsums + depth-4 load ring; parity-staggered flag stream.
// Fallback (never taken for dense inputs) uses a global scratch buffer so
// block smem stays small (~11.5 KB) for 8-block occupancy.
// ---------------------------------------------------------------------------

#define B_TOT   4096
#define BANDS   5
#define NN      30
#define IN_C    512
#define FF      128
#define CC      9
#define TB      4             // batches per block
#define SB      6             // padded batch stride (floats) in k-major smem

typedef unsigned long long u64t;

// ---- f32x2 helpers --------------------------------------------------------
__device__ __forceinline__ u64t pk2(float lo, float hi) {
    u64t r; asm("mov.b64 %0,{%1,%2};" : "=l"(r) : "f"(lo), "f"(hi)); return r;
}
__device__ __forceinline__ void upk2(float& lo, float& hi, u64t v) {
    asm("mov.b64 {%0,%1},%2;" : "=f"(lo), "=f"(hi) : "l"(v));
}
__device__ __forceinline__ void fma2(u64t& d, u64t a, u64t b) {
    asm("fma.rn.f32x2 %0,%1,%2,%0;" : "+l"(d) : "l"(a), "l"(b));
}

// global scratch for the (never-taken-in-practice) honest fallback path.
__device__ float g_fbscratch[B_TOT / TB][9216];

// ---------------------------------------------------------------------------
// graph density flags for this block's TB batches (128 threads).
// ---------------------------------------------------------------------------
__device__ __forceinline__ void flags_check(
    int b0, int tid, const float* __restrict__ graph, int* flagS)
{
    for (int i = tid; i < TB * 225; i += 128) {
        int b = i / 225, idx = i - b * 225;
        const float4* g4 = (const float4*)(graph + (size_t)(b0 + b) * (BANDS * NN * NN));
        float4 a0 = g4[idx];
        float4 a1 = g4[225 + idx];
        float4 a2 = g4[450 + idx];
        float4 a3 = g4[675 + idx];
        float4 a4 = g4[900 + idx];
        float s[4];
        s[0] = a0.x + a1.x + a2.x + a3.x + a4.x;
        s[1] = a0.y + a1.y + a2.y + a3.y + a4.y;
        s[2] = a0.z + a1.z + a2.z + a3.z + a4.z;
        s[3] = a0.w + a1.w + a2.w + a3.w + a4.w;
        bool bad = false;
        #pragma unroll
        for (int j = 0; j < 4; j++) {
            int p = idx * 4 + j;
            int n = p / NN, m = p - n * NN;
            if (n != m && s[j] * 0.2f == 0.0f) bad = true;
        }
        if (bad) flagS[b] = 0;
    }
}

// ---------------------------------------------------------------------------
// honest fallback for one non-dense batch; 128 threads, global scratch.
// (__syncthreads() fences the block's global writes, so the shared-memory
// protocol carries over to the global scratch unchanged.)
// ---------------------------------------------------------------------------
__device__ void fallback_batch(
    int b, float* S, int tid,
    const float* __restrict__ real, const float* __restrict__ graph,
    const float* __restrict__ W1, const float* __restrict__ b1,
    const float* __restrict__ W2, const float* __restrict__ b2,
    const float* __restrict__ Wlin, const float* __restrict__ blin,
    const float* __restrict__ Wconv, const float* __restrict__ bconv,
    float* __restrict__ out)
{
    float* An   = S;                    // 900 (pad to 960 incl. dinv)
    float* dinv = S + 900;              // 30
    float* Ys   = S + 960;              // 3840
    float* Hs   = Ys + 3840;            // 3840
    float* rrow = Hs + 3840;            // 512
    float* xsb  = rrow + 512;           // 30

    const float* g = graph + (size_t)b * (BANDS * NN * NN);
    for (int p = tid; p < NN * NN; p += 128) {
        int n = p / NN, m = p - n * NN;
        float s5 = g[p] + g[900 + p] + g[1800 + p] + g[2700 + p] + g[3600 + p];
        float a = (s5 * 0.2f != 0.0f) ? 1.0f : 0.0f;
        if (n == m) a = 1.0f;
        An[p] = a;
    }
    __syncthreads();
    if (tid < NN) {
        float dg = 0.f;
        for (int m = 0; m < NN; m++) dg += An[tid * NN + m];
        dinv[tid] = (dg > 0.f) ? rsqrtf(dg) : 0.0f;
    }
    __syncthreads();
    for (int p = tid; p < NN * NN; p += 128) {
        int n = p / NN, m = p - n * NN;
        An[p] = dinv[n] * An[p] * dinv[m];
    }
    __syncthreads();

    const float* rb = real + (size_t)b * NN * IN_C;
    for (int n = 0; n < NN; n++) {
        for (int c = tid; c < IN_C; c += 128) rrow[c] = rb[n * IN_C + c];
        __syncthreads();
        {
            float accv = 0.f;
            for (int c = 0; c < IN_C; c++) accv += rrow[c] * W1[c * FF + tid];
            Ys[n * FF + tid] = accv;
        }
        __syncthreads();
    }
    {
        float bb = b1[tid];
        for (int n = 0; n < NN; n++) {
            float accv = 0.f;
            for (int m = 0; m < NN; m++) accv += An[n * NN + m] * Ys[m * FF + tid];
            Hs[n * FF + tid] = fmaxf(accv + bb, 0.0f);
        }
    }
    __syncthreads();
    for (int n = 0; n < NN; n++) {
        float accv = 0.f;
        for (int c = 0; c < FF; c++) accv += Hs[n * FF + c] * W2[c * FF + tid];
        Ys[n * FF + tid] = accv;
    }
    __syncthreads();
    {
        float bb = b2[tid];
        for (int n = 0; n < NN; n++) {
            float accv = 0.f;
            for (int m = 0; m < NN; m++) accv += An[n * NN + m] * Ys[m * FF + tid];
            Hs[n * FF + tid] = fmaxf(accv + bb, 0.0f);
        }
    }
    __syncthreads();
    if (tid < NN) {
        float accv = 0.f;
        for (int ff = 0; ff < FF; ff++) accv += Hs[tid * FF + ff] * Wlin[ff];
        xsb[tid] = fmaxf(accv + blin[0], 0.0f);
    }
    __syncthreads();
    if (tid < CC) {
        float accv = bconv[tid];
        for (int n = 0; n < NN; n++) accv += xsb[n] * Wconv[tid * NN + n];
        out[(size_t)b * CC + tid] = accv;
    }
    __syncthreads();
}

// ---------------------------------------------------------------------------
// fused kernel: grid 1024, block 128, TB=4 batches/block, 8 blocks/SM.
// Warp w (0..3): FMA role = k-quarter w (all 4 batches); streams batch w.
// Lane: features f = 4*lane.
// ---------------------------------------------------------------------------
__global__ void __launch_bounds__(128, 8) fused_gcn(
    const float* __restrict__ real, const float* __restrict__ graph,
    const float* __restrict__ W1, const float* __restrict__ b1,
    const float* __restrict__ W2, const float* __restrict__ b2,
    const float* __restrict__ Wlin, const float* __restrict__ blin,
    const float* __restrict__ Wconv, const float* __restrict__ bconv,
    float* __restrict__ out)
{
    // buf (11264 B, time-multiplexed):
    //   ubuf0 [128][SB] @ 0    (3072 B)   | red64 [4 q][2 g][128 f] u64 @ 0
    //   ubuf1 [128][SB] @ 3072 (3072 B)   |   (8192 B; after chunk loop)
    //   h1T   [128][SB] @ 8192 (3072 B)   (disjoint from red64)
    __shared__ __align__(16) char buf[11264];
    __shared__ float xp[4][4];
    __shared__ float xs[TB];
    __shared__ float wsum[CC];
    __shared__ int   flagS[TB];

    float* ub0   = (float*)buf;
    float* ub1   = (float*)(buf + 3072);
    u64t*  red64 = (u64t*)buf;
    float* h1T   = (float*)(buf + 8192);

    const int tid  = threadIdx.x;
    const int b0   = blockIdx.x * TB;
    const int w    = tid >> 5;          // warp 0..3
    const int lane = tid & 31;
    const int f4   = lane * 4;
    const bool flags_early = ((blockIdx.x & 1) == 0);

    if (tid < TB) flagS[tid] = 1;
    if (tid < CC) {
        float a = 0.f;
        #pragma unroll
        for (int n = 0; n < NN; n++) a += Wconv[tid * NN + n];
        wsum[tid] = a;
    }
    __syncthreads();

    // ---- flags: even blocks now, odd blocks after layer-2 (R10 stagger)
    if (flags_early)
        flags_check(b0, tid, graph, flagS);

    // ---- layer-1 pipeline over 4 K-chunks of 128.
    const float4* rb4 = (const float4*)(real + (size_t)(b0 + w) * NN * IN_C);

    // prologue: colsum of chunk 0 -> ub0 (warp w owns batch w)
    {
        float4 a = make_float4(0.f, 0.f, 0.f, 0.f);
        #pragma unroll 6
        for (int n = 0; n < NN; n++) {
            float4 v = rb4[n * (IN_C / 4) + lane];
            a.x += v.x; a.y += v.y; a.z += v.z; a.w += v.w;
        }
        int kb = lane * 4;
        ub0[(kb + 0) * SB + w] = a.x;
        ub0[(kb + 1) * SB + w] = a.y;
        ub0[(kb + 2) * SB + w] = a.z;
        ub0[(kb + 3) * SB + w] = a.w;
    }
    __syncthreads();

    u64t acc[2][4];                     // [pair p: batches {2p,2p+1}][feat j]
    #pragma unroll
    for (int p = 0; p < 2; p++)
        #pragma unroll
        for (int j = 0; j < 4; j++) acc[p][j] = 0ull;

    for (int c = 0; c < 4; c++) {
        float* ub = (c & 1) ? ub1 : ub0;
        float* un = (c & 1) ? ub0 : ub1;
        const bool more = (c < 3);
        const float4* nxt = rb4 + (c + 1) * 32 + lane;    // rows of next chunk
        float4 a = make_float4(0.f, 0.f, 0.f, 0.f);
        const int kbeg = w * 32;                          // k-quarter in chunk
        const float4* Wp = (const float4*)(W1 + (size_t)(c * 128 + kbeg) * FF) + lane;
        float4 wpf[2];
        wpf[0] = Wp[0];
        wpf[1] = Wp[FF / 4];

        // depth-4 ring on streamed loads: slot ki&3 holds row ki.
        float4 vr[4];
        if (more) {
            #pragma unroll
            for (int s = 0; s < 4; s++) vr[s] = nxt[s * (IN_C / 4)];
        }
        #pragma unroll
        for (int ki = 0; ki < 32; ki++) {
            float4 v;
            bool cons = more && (ki < NN);
            if (cons) v = vr[ki & 3];
            if (more && (ki + 4 < NN))
                vr[ki & 3] = nxt[(ki + 4) * (IN_C / 4)];
            float4 wv = wpf[ki & 1];
            if (ki + 2 < 32) wpf[ki & 1] = Wp[(ki + 2) * (FF / 4)];
            const float* up = &ub[(kbeg + ki) * SB];
            u64t u0 = *(const u64t*)(up + 0);   // batches 0,1
            u64t u1 = *(const u64t*)(up + 2);   // batches 2,3
            u64t w0 = pk2(wv.x, wv.x), w1 = pk2(wv.y, wv.y);
            u64t w2 = pk2(wv.z, wv.z), w3 = pk2(wv.w, wv.w);
            fma2(acc[0][0], u0, w0); fma2(acc[1][0], u1, w0);
            fma2(acc[0][1], u0, w1); fma2(acc[1][1], u1, w1);
            fma2(acc[0][2], u0, w2); fma2(acc[1][2], u1, w2);
            fma2(acc[0][3], u0, w3); fma2(acc[1][3], u1, w3);
            if (cons) { a.x += v.x; a.y += v.y; a.z += v.z; a.w += v.w; }
        }
        // write next-chunk colsum to un: safe without a barrier — un's last
        // readers finished before the barrier that ended chunk c-1.
        if (more) {
            int kb = lane * 4;
            un[(kb + 0) * SB + w] = a.x;
            un[(kb + 1) * SB + w] = a.y;
            un[(kb + 2) * SB + w] = a.z;
            un[(kb + 3) * SB + w] = a.w;
        }
        __syncthreads();          // un visible; ub reads done for next reuse
    }

    // ---- stash layer-1 partials (red64 aliases the dead ubuf region)
    #pragma unroll
    for (int p = 0; p < 2; p++)
        #pragma unroll
        for (int j = 0; j < 4; j++)
            red64[w * 256 + p * 128 + f4 + j] = acc[p][j];
    __syncthreads();

    // ---- reduce q -> h1T (h1T disjoint from red64: no extra barrier).
    {
        const float s1 = 1.0f / 30.0f;
        float bb = b1[tid];
        #pragma unroll
        for (int g = 0; g < 2; g++) {
            float lo = 0.f, hi = 0.f;
            #pragma unroll
            for (int q = 0; q < 4; q++) {
                float av, bv; upk2(av, bv, red64[q * 256 + g * 128 + tid]);
                lo += av; hi += bv;
            }
            h1T[tid * SB + 2 * g]     = fmaxf(fmaf(s1, lo, bb), 0.0f);
            h1T[tid * SB + 2 * g + 1] = fmaxf(fmaf(s1, hi, bb), 0.0f);
        }
    }
    __syncthreads();

    // ---- layer-2 partials. Warp w: k in [32w, 32w+32), all 4 batches.
    #pragma unroll
    for (int p = 0; p < 2; p++)
        #pragma unroll
        for (int j = 0; j < 4; j++) acc[p][j] = 0ull;
    {
        const int kbeg = w * 32;
        const float4* Wp = (const float4*)(W2 + (size_t)kbeg * FF) + lane;
        float4 wpf[2];
        wpf[0] = Wp[0];
        wpf[1] = Wp[FF / 4];
        #pragma unroll 4
        for (int ki = 0; ki < 32; ki++) {
            float4 wv = wpf[ki & 1];
            int kn = (ki + 2 < 32) ? (ki + 2) : ki;
            wpf[ki & 1] = Wp[kn * (FF / 4)];
            const float* up = &h1T[(kbeg + ki) * SB];
            u64t u0 = *(const u64t*)(up + 0);
            u64t u1 = *(const u64t*)(up + 2);
            u64t w0 = pk2(wv.x, wv.x), w1 = pk2(wv.y, wv.y);
            u64t w2 = pk2(wv.z, wv.z), w3 = pk2(wv.w, wv.w);
            fma2(acc[0][0], u0, w0); fma2(acc[1][0], u1, w0);
            fma2(acc[0][1], u0, w1); fma2(acc[1][1], u1, w1);
            fma2(acc[0][2], u0, w2); fma2(acc[1][2], u1, w2);
            fma2(acc[0][3], u0, w3); fma2(acc[1][3], u1, w3);
        }
    }
    // red64 (layer-2) disjoint from h1T: no barrier needed before writing.
    #pragma unroll
    for (int p = 0; p < 2; p++)
        #pragma unroll
        for (int j = 0; j < 4; j++)
            red64[w * 256 + p * 128 + f4 + j] = acc[p][j];

    // ---- flags for odd blocks: streams DRAM during others' compute tails.
    if (!flags_early)
        flags_check(b0, tid, graph, flagS);
    __syncthreads();

    // ---- final reduce + epilogue. Thread tid = feature f.
    {
        float bb = b2[tid];
        float wl = Wlin[tid];
        float part[4];                    // slot 2g+e = batch
        #pragma unroll
        for (int g = 0; g < 2; g++) {
            float lo = 0.f, hi = 0.f;
            #pragma unroll
            for (int q = 0; q < 4; q++) {
                float av, bv; upk2(av, bv, red64[q * 256 + g * 128 + tid]);
                lo += av; hi += bv;
            }
            part[2 * g]     = fmaxf(lo + bb, 0.0f) * wl;
            part[2 * g + 1] = fmaxf(hi + bb, 0.0f) * wl;
        }
        #pragma unroll
        for (int off = 16; off > 0; off >>= 1)
            #pragma unroll
            for (int s = 0; s < 4; s++)
                part[s] += __shfl_xor_sync(0xffffffffu, part[s], off);
        if (lane == 0) {
            xp[w][0] = part[0]; xp[w][1] = part[1];
            xp[w][2] = part[2]; xp[w][3] = part[3];
        }
    }
    __syncthreads();
    if (tid < TB) {
        float s = xp[0][tid] + xp[1][tid] + xp[2][tid] + xp[3][tid];
        xs[tid] = fmaxf(s + blin[0], 0.0f);
    }
    __syncthreads();

    if (tid < TB * CC) {
        int b = tid / CC, c = tid - b * CC;
        if (flagS[b])
            out[(size_t)(b0 + b) * CC + c] = xs[b] * wsum[c] + bconv[c];
    }
    __syncthreads();

    // ---- honest fallback for any non-dense batch (uniform branch)
    for (int fb = 0; fb < TB; fb++) {
        if (!flagS[fb]) {
            fallback_batch(b0 + fb, g_fbscratch[blockIdx.x], tid, real, graph,
                           W1, b1, W2, b2, Wlin, blin, Wconv, bconv, out);
        }
    }
}

// ---------------------------------------------------------------------------
extern "C" void kernel_launch(void* const* d_in, const int* in_sizes, int n_in,
                              void* d_out, int out_size)
{
    const float* real  = (const float*)d_in[0];
    const float* graph = (const float*)d_in[2];
    const float* W1    = (const float*)d_in[3];
    const float* b1    = (const float*)d_in[4];
    const float* W2    = (const float*)d_in[5];
    const float* b2    = (const float*)d_in[6];
    const float* Wlin  = (const float*)d_in[7];
    const float* blin  = (const float*)d_in[8];
    const float* Wconv = (const float*)d_in[9];
    const float* bconv = (const float*)d_in[10];
    float* out = (float*)d_out;

    fused_gcn<<<B_TOT / TB, 128>>>(real, graph, W1, b1, W2, b2, Wlin, blin,
                                   Wconv, bconv, out);
}